// round 1
// baseline (speedup 1.0000x reference)
#include <cuda_runtime.h>

#define B   64
#define H   480
#define W   640
#define PH  64
#define PW  512
#define FS  15
#define NF  7
#define RAD 7            // FS/2

#define K_TOT   (PH*PW)          // 32768 feats columns
#define N_ROWS  (B*NF)           // 448 feats rows
#define NTILES  7                // 448/64
#define NPAIRS  28               // upper-triangular tile pairs
#define KSPLIT  16
#define KCHUNK  (K_TOT/KSPLIT)   // 2048

#define CODES_OFF 0
#define GRAM_OFF  (B*NF*PH*PW)           // 14680064
#define POLAR_OFF (GRAM_OFF + N_ROWS*N_ROWS) // 14880768

// deterministic K-split scratch: [pair][ksplit][64*64]
__device__ float g_partial[NPAIRS][KSPLIT][64*64];

// ---------------------------------------------------------------------------
// Kernel 1: polar bilinear resample (replicates reference coord math exactly)
// ---------------------------------------------------------------------------
__global__ void polar_kernel(const float* __restrict__ img,
                             const float* __restrict__ pupil,
                             const float* __restrict__ iris,
                             float* __restrict__ polar) {
    int idx = blockIdx.x * blockDim.x + threadIdx.x;
    if (idx >= B * PH * PW) return;
    int col = idx % PW;
    int row = (idx / PW) % PH;
    int b   = idx / (PH * PW);

    float theta = 6.283185307179586f * (float)(col + 1) * (1.0f / (float)PW);
    float ct = cosf(theta), st = sinf(theta);

    float pcx = pupil[b*3+0], pcy = pupil[b*3+1], pr = pupil[b*3+2];
    float icx = iris [b*3+0], icy = iris [b*3+1], ir = iris [b*3+2];

    float px = pcx + pr * ct;
    float py = pcy + pr * st;
    float ix = icx + ir * ct;
    float iy = icy + ir * st;

    float rad = (float)row / (float)(PH - 1);
    float xg = (1.0f - rad) * px + rad * ix;
    float yg = (1.0f - rad) * py + rad * iy;

    float x = fminf(fmaxf(xg, 0.0f), (float)(W - 1));
    float y = fminf(fmaxf(yg, 0.0f), (float)(H - 1));

    // reference's double normalization, kept verbatim
    float xn = x / (float)(W - 1) * 2.0f - 1.0f;
    float yn = y / (float)(H - 1) * 2.0f - 1.0f;
    float gx = ((xn + 1.0f) * 0.5f * (float)W - 0.5f) / (float)(W - 1) * 2.0f - 1.0f;
    float gy = ((yn + 1.0f) * 0.5f * (float)H - 0.5f) / (float)(H - 1) * 2.0f - 1.0f;
    float sx = ((gx + 1.0f) * (float)W - 1.0f) * 0.5f;
    float sy = ((gy + 1.0f) * (float)H - 1.0f) * 0.5f;

    float x0f = floorf(sx), y0f = floorf(sy);
    float wx = sx - x0f, wy = sy - y0f;
    int x0 = (int)x0f, y0 = (int)y0f;

    const float* im = img + (size_t)b * H * W;

    float v00 = 0.f, v01 = 0.f, v10 = 0.f, v11 = 0.f;
    bool xv0 = (x0 >= 0) && (x0 < W);
    bool xv1 = (x0+1 >= 0) && (x0+1 < W);
    bool yv0 = (y0 >= 0) && (y0 < H);
    bool yv1 = (y0+1 >= 0) && (y0+1 < H);
    int x0c = min(max(x0, 0), W-1), x1c = min(max(x0+1, 0), W-1);
    int y0c = min(max(y0, 0), H-1), y1c = min(max(y0+1, 0), H-1);
    if (xv0 && yv0) v00 = im[y0c*W + x0c] * 255.0f;
    if (xv1 && yv0) v01 = im[y0c*W + x1c] * 255.0f;
    if (xv0 && yv1) v10 = im[y1c*W + x0c] * 255.0f;
    if (xv1 && yv1) v11 = im[y1c*W + x1c] * 255.0f;

    float v = v00*(1.0f-wx)*(1.0f-wy) + v01*wx*(1.0f-wy)
            + v10*(1.0f-wx)*wy        + v11*wx*wy;
    polar[idx] = v;
}

// ---------------------------------------------------------------------------
// Kernel 2: 15x15 wrap conv, 7 filters. Block = (32,8) computing a 32x8 tile.
// codes[b,o,y,x] = sum_{i,j} filter[i,j,6-o] * polar[b,(y-7+i)%64,(x-7+j)%512]
// ---------------------------------------------------------------------------
__global__ void conv_kernel(const float* __restrict__ polar,
                            const float* __restrict__ filt,
                            float* __restrict__ codes) {
    __shared__ float tile[22 * 48];              // 22 rows x 46 cols, stride 48
    __shared__ __align__(16) float fsm[FS*FS*8]; // filter padded to 8 per tap

    int tx = threadIdx.x;            // 0..31
    int ty = threadIdx.y;            // 0..7
    int tid = ty * 32 + tx;          // 0..255
    int bx = blockIdx.x;             // 0..15  (x tiles of 32)
    int by = blockIdx.y;             // 0..7   (y tiles of 8)
    int b  = blockIdx.z;             // 0..63

    // load filter into padded smem: fsm[(i*15+j)*8 + f] = filt[(i*15+j)*7 + f]
    for (int e = tid; e < FS*FS*NF; e += 256) {
        int tap = e / NF, f = e % NF;
        fsm[tap*8 + f] = filt[e];
    }
    // load input tile with wrap halo
    const float* pb = polar + (size_t)b * PH * PW;
    for (int e = tid; e < 22 * 46; e += 256) {
        int rr = e / 46, cc = e % 46;
        int gy = (by*8 + 64 - RAD + rr) & (PH - 1);
        int gx = (bx*32 + 512 - RAD + cc) & (PW - 1);
        tile[rr*48 + cc] = pb[gy * PW + gx];
    }
    __syncthreads();

    float acc0=0.f,acc1=0.f,acc2=0.f,acc3=0.f,acc4=0.f,acc5=0.f,acc6=0.f;
    for (int i = 0; i < FS; i++) {
        const float* trow = &tile[(ty + i) * 48 + tx];
        const float* frow = &fsm[(i * FS) * 8];
        #pragma unroll
        for (int j = 0; j < FS; j++) {
            float p = trow[j];
            float4 w0 = *(const float4*)&frow[j*8];
            float4 w1 = *(const float4*)&frow[j*8 + 4];
            acc0 += w0.x * p;
            acc1 += w0.y * p;
            acc2 += w0.z * p;
            acc3 += w0.w * p;
            acc4 += w1.x * p;
            acc5 += w1.y * p;
            acc6 += w1.z * p;
        }
    }

    int y = by*8 + ty;
    int x = bx*32 + tx;
    size_t base = ((size_t)b * NF) * PH * PW + (size_t)y * PW + x;
    // channel o = 6 - f
    codes[base + (size_t)(6-0)*PH*PW] = acc0;
    codes[base + (size_t)(6-1)*PH*PW] = acc1;
    codes[base + (size_t)(6-2)*PH*PW] = acc2;
    codes[base + (size_t)(6-3)*PH*PW] = acc3;
    codes[base + (size_t)(6-4)*PH*PW] = acc4;
    codes[base + (size_t)(6-5)*PH*PW] = acc5;
    codes[base + (size_t)(6-6)*PH*PW] = acc6;
}

// ---------------------------------------------------------------------------
// Kernel 3: gram partials. Grid (28 pairs, 16 K-splits), 256 threads.
// Each block: 64x64 tile over a 2048-K chunk, 4x4 per-thread micro-tile.
// ---------------------------------------------------------------------------
__global__ void gram_partial_kernel(const float* __restrict__ feats) {
    __shared__ __align__(16) float As[32][68];
    __shared__ __align__(16) float Bs[32][68];

    int pair = blockIdx.x;
    int ksp  = blockIdx.y;

    // pair -> (ti, tj), ti <= tj
    int ti = 0, rem = pair, cnt = NTILES;
    while (rem >= cnt) { rem -= cnt; ti++; cnt--; }
    int tj = ti + rem;

    int t  = threadIdx.x;     // 0..255
    int tx = t & 15;          // 0..15
    int ty = t >> 4;          // 0..15

    float acc[4][4];
    #pragma unroll
    for (int r = 0; r < 4; r++)
        #pragma unroll
        for (int c = 0; c < 4; c++) acc[r][c] = 0.f;

    const float* arow = feats + (size_t)(ti * 64) * K_TOT + ksp * KCHUNK;
    const float* brow = feats + (size_t)(tj * 64) * K_TOT + ksp * KCHUNK;

    for (int kc = 0; kc < KCHUNK; kc += 32) {
        #pragma unroll
        for (int l = 0; l < 8; l++) {
            int e  = t + l * 256;
            int kk = e & 31;
            int ii = e >> 5;
            As[kk][ii] = arow[(size_t)ii * K_TOT + kc + kk];
            Bs[kk][ii] = brow[(size_t)ii * K_TOT + kc + kk];
        }
        __syncthreads();
        #pragma unroll
        for (int kk = 0; kk < 32; kk++) {
            float4 a = *(const float4*)&As[kk][ty * 4];
            float4 bq = *(const float4*)&Bs[kk][tx * 4];
            acc[0][0] += a.x * bq.x; acc[0][1] += a.x * bq.y;
            acc[0][2] += a.x * bq.z; acc[0][3] += a.x * bq.w;
            acc[1][0] += a.y * bq.x; acc[1][1] += a.y * bq.y;
            acc[1][2] += a.y * bq.z; acc[1][3] += a.y * bq.w;
            acc[2][0] += a.z * bq.x; acc[2][1] += a.z * bq.y;
            acc[2][2] += a.z * bq.z; acc[2][3] += a.z * bq.w;
            acc[3][0] += a.w * bq.x; acc[3][1] += a.w * bq.y;
            acc[3][2] += a.w * bq.z; acc[3][3] += a.w * bq.w;
        }
        __syncthreads();
    }

    float* dst = &g_partial[pair][ksp][0];
    #pragma unroll
    for (int r = 0; r < 4; r++)
        #pragma unroll
        for (int c = 0; c < 4; c++)
            dst[(ty*4 + r) * 64 + tx*4 + c] = acc[r][c];
}

// ---------------------------------------------------------------------------
// Kernel 4: deterministic K-split reduction + scale + symmetric write
// ---------------------------------------------------------------------------
__global__ void gram_reduce_kernel(float* __restrict__ gram) {
    int idx = blockIdx.x * blockDim.x + threadIdx.x;
    if (idx >= NPAIRS * 64 * 64) return;
    int pair = idx / 4096;
    int e    = idx % 4096;
    int ii = e / 64, jj = e % 64;

    int ti = 0, rem = pair, cnt = NTILES;
    while (rem >= cnt) { rem -= cnt; ti++; cnt--; }
    int tj = ti + rem;

    float s = 0.f;
    #pragma unroll
    for (int k = 0; k < KSPLIT; k++) s += g_partial[pair][k][e];
    s *= (1.0f / (float)((size_t)N_ROWS * K_TOT));   // 1/14680064

    int i = ti * 64 + ii;
    int j = tj * 64 + jj;
    gram[i * N_ROWS + j] = s;
    gram[j * N_ROWS + i] = s;
}

// ---------------------------------------------------------------------------
extern "C" void kernel_launch(void* const* d_in, const int* in_sizes, int n_in,
                              void* d_out, int out_size) {
    const float* image = (const float*)d_in[0];
    const float* pupil = (const float*)d_in[1];
    const float* iris  = (const float*)d_in[2];
    const float* filt  = (const float*)d_in[3];

    float* out   = (float*)d_out;
    float* codes = out + CODES_OFF;
    float* gram  = out + GRAM_OFF;
    float* polar = out + POLAR_OFF;

    polar_kernel<<<(B * PH * PW) / 256, 256>>>(image, pupil, iris, polar);
    conv_kernel<<<dim3(PW/32, PH/8, B), dim3(32, 8)>>>(polar, filt, codes);
    gram_partial_kernel<<<dim3(NPAIRS, KSPLIT), 256>>>(codes);
    gram_reduce_kernel<<<(NPAIRS * 4096) / 256, 256>>>(gram);
}

// round 3
// speedup vs baseline: 1.7666x; 1.7666x over previous
#include <cuda_runtime.h>
#include <cuda_bf16.h>
#include <cstdint>

#define B   64
#define H   480
#define W   640
#define PH  64
#define PW  512
#define FS  15
#define NF  7
#define RAD 7

#define K_TOT   (PH*PW)          // 32768
#define N_ROWS  (B*NF)           // 448

#define CODES_OFF 0
#define GRAM_OFF  (B*NF*PH*PW)                // 14680064
#define POLAR_OFF (GRAM_OFF + N_ROWS*N_ROWS)  // 14880768

// ---- gram tiling ----
#define GT       4                  // 128-row tiles (448 padded to 512)
#define GPAIRS   10                 // upper-tri tile pairs
#define GKSPLIT  32
#define GKCHUNK  (K_TOT/GKSPLIT)    // 1024
#define KB       32                 // k per smem stage
#define KITERS   (GKCHUNK/KB)       // 32

#define TSTRIDE  40                 // bf16 per smem row (80 B) -> conflict-free ldmatrix
#define TILE_BF  (128*TSTRIDE)      // 5120 bf16 per matrix tile
#define TILE_BY  (TILE_BF*2)        // 10240 B
#define STAGE_BY (4*TILE_BY)        // Ahi|Alo|Bhi|Blo = 40960 B
#define GSMEM    (2*STAGE_BY)       // 81920 B

// scratch
__device__ __nv_bfloat16 g_hi[(size_t)N_ROWS * K_TOT];
__device__ __nv_bfloat16 g_lo[(size_t)N_ROWS * K_TOT];
__device__ float g_gpart[GPAIRS][GKSPLIT][128*128];

// ===========================================================================
// helpers
// ===========================================================================
__device__ __forceinline__ uint32_t smem_u32(const void* p) {
    uint32_t a;
    asm("{ .reg .u64 t; cvta.to.shared.u64 t, %1; cvt.u32.u64 %0, t; }" : "=r"(a) : "l"(p));
    return a;
}

#define FFMA2(d, a, b) \
    asm("fma.rn.f32x2 %0, %1, %2, %0;" : "+l"(d) : "l"(a), "l"(b))
#define DUP2(d, s) \
    asm("mov.b64 %0, {%1, %1};" : "=l"(d) : "f"(s))
#define UNPK2(lo, hi, v) \
    asm("mov.b64 {%0, %1}, %2;" : "=f"(lo), "=f"(hi) : "l"(v))

__device__ __forceinline__ void cp16(uint32_t dst, const void* src) {
    asm volatile("cp.async.ca.shared.global [%0], [%1], 16;" :: "r"(dst), "l"(src));
}
__device__ __forceinline__ void cp16z(uint32_t dst, const void* src) {
    asm volatile("cp.async.ca.shared.global [%0], [%1], 16, 0;" :: "r"(dst), "l"(src));
}
__device__ __forceinline__ void cp_commit() { asm volatile("cp.async.commit_group;" ::: "memory"); }
__device__ __forceinline__ void cp_wait1()  { asm volatile("cp.async.wait_group 1;" ::: "memory"); }
__device__ __forceinline__ void cp_wait0()  { asm volatile("cp.async.wait_group 0;" ::: "memory"); }

__device__ __forceinline__ void ldm_x4(uint32_t* r, uint32_t addr) {
    asm volatile("ldmatrix.sync.aligned.m8n8.x4.shared.b16 {%0,%1,%2,%3}, [%4];"
        : "=r"(r[0]), "=r"(r[1]), "=r"(r[2]), "=r"(r[3]) : "r"(addr));
}
__device__ __forceinline__ void ldm_x2(uint32_t* r, uint32_t addr) {
    asm volatile("ldmatrix.sync.aligned.m8n8.x2.shared.b16 {%0,%1}, [%2];"
        : "=r"(r[0]), "=r"(r[1]) : "r"(addr));
}
__device__ __forceinline__ void mma_bf16(float* c, const uint32_t* a, const uint32_t* b) {
    asm volatile("mma.sync.aligned.m16n8k16.row.col.f32.bf16.bf16.f32 "
        "{%0,%1,%2,%3}, {%4,%5,%6,%7}, {%8,%9}, {%0,%1,%2,%3};"
        : "+f"(c[0]), "+f"(c[1]), "+f"(c[2]), "+f"(c[3])
        : "r"(a[0]), "r"(a[1]), "r"(a[2]), "r"(a[3]), "r"(b[0]), "r"(b[1]));
}

// ===========================================================================
// Kernel 1: polar bilinear resample
// ===========================================================================
__global__ void polar_kernel(const float* __restrict__ img,
                             const float* __restrict__ pupil,
                             const float* __restrict__ iris,
                             float* __restrict__ polar) {
    int idx = blockIdx.x * blockDim.x + threadIdx.x;
    if (idx >= B * PH * PW) return;
    int col = idx % PW;
    int row = (idx / PW) % PH;
    int b   = idx / (PH * PW);

    float theta = 6.283185307179586f * (float)(col + 1) * (1.0f / (float)PW);
    float ct = cosf(theta), st = sinf(theta);

    float pcx = pupil[b*3+0], pcy = pupil[b*3+1], pr = pupil[b*3+2];
    float icx = iris [b*3+0], icy = iris [b*3+1], ir = iris [b*3+2];

    float px = pcx + pr * ct;
    float py = pcy + pr * st;
    float ix = icx + ir * ct;
    float iy = icy + ir * st;

    float rad = (float)row / (float)(PH - 1);
    float xg = (1.0f - rad) * px + rad * ix;
    float yg = (1.0f - rad) * py + rad * iy;

    float x = fminf(fmaxf(xg, 0.0f), (float)(W - 1));
    float y = fminf(fmaxf(yg, 0.0f), (float)(H - 1));

    float xn = x / (float)(W - 1) * 2.0f - 1.0f;
    float yn = y / (float)(H - 1) * 2.0f - 1.0f;
    float gx = ((xn + 1.0f) * 0.5f * (float)W - 0.5f) / (float)(W - 1) * 2.0f - 1.0f;
    float gy = ((yn + 1.0f) * 0.5f * (float)H - 0.5f) / (float)(H - 1) * 2.0f - 1.0f;
    float sx = ((gx + 1.0f) * (float)W - 1.0f) * 0.5f;
    float sy = ((gy + 1.0f) * (float)H - 1.0f) * 0.5f;

    float x0f = floorf(sx), y0f = floorf(sy);
    float wx = sx - x0f, wy = sy - y0f;
    int x0 = (int)x0f, y0 = (int)y0f;

    const float* im = img + (size_t)b * H * W;

    float v00 = 0.f, v01 = 0.f, v10 = 0.f, v11 = 0.f;
    bool xv0 = (x0 >= 0) && (x0 < W);
    bool xv1 = (x0+1 >= 0) && (x0+1 < W);
    bool yv0 = (y0 >= 0) && (y0 < H);
    bool yv1 = (y0+1 >= 0) && (y0+1 < H);
    int x0c = min(max(x0, 0), W-1), x1c = min(max(x0+1, 0), W-1);
    int y0c = min(max(y0, 0), H-1), y1c = min(max(y0+1, 0), H-1);
    if (xv0 && yv0) v00 = im[y0c*W + x0c] * 255.0f;
    if (xv1 && yv0) v01 = im[y0c*W + x1c] * 255.0f;
    if (xv0 && yv1) v10 = im[y1c*W + x0c] * 255.0f;
    if (xv1 && yv1) v11 = im[y1c*W + x1c] * 255.0f;

    float v = v00*(1.0f-wx)*(1.0f-wy) + v01*wx*(1.0f-wy)
            + v10*(1.0f-wx)*wy        + v11*wx*wy;
    polar[idx] = v;
}

// ===========================================================================
// Kernel 2: 15x15 wrap conv with fma.rn.f32x2. Block (8,32): 8 px each thread.
// ===========================================================================
#define CSTRIDE 80
__global__ __launch_bounds__(256, 2)
void conv_kernel(const float* __restrict__ polar,
                 const float* __restrict__ filt,
                 float* __restrict__ codes) {
    __shared__ __align__(16) float tile[46 * CSTRIDE];
    __shared__ __align__(16) float fsm2f[FS*FS*8];

    int tx = threadIdx.x;            // 0..7
    int ty = threadIdx.y;            // 0..31
    int tid = ty * 8 + tx;
    int bx = blockIdx.x;             // 0..7
    int by = blockIdx.y;             // 0..1
    int b  = blockIdx.z;

    for (int e = tid; e < FS*FS*8; e += 256) {
        int tap = e >> 3, f = e & 7;
        fsm2f[e] = (f < NF) ? filt[tap*NF + f] : 0.0f;
    }
    const float* pb = polar + (size_t)b * PH * PW;
    for (int e = tid; e < 46 * 78; e += 256) {
        int rr = e / 78, cc = e % 78;
        int gy = (by*32 + 64 - RAD + rr) & (PH - 1);
        int gx = (bx*64 + 512 - RAD + cc) & (PW - 1);
        tile[rr*CSTRIDE + cc] = pb[gy * PW + gx];
    }
    __syncthreads();

    unsigned long long acc[8][4];
    #pragma unroll
    for (int p = 0; p < 8; p++)
        #pragma unroll
        for (int q = 0; q < 4; q++) acc[p][q] = 0ULL;

    for (int i = 0; i < FS; i++) {
        const float* rowp = &tile[(ty + i) * CSTRIDE + tx * 8];
        unsigned long long d[8];
        float4 w0 = *(const float4*)rowp;
        float4 w1 = *(const float4*)(rowp + 4);
        DUP2(d[0], w0.x); DUP2(d[1], w0.y); DUP2(d[2], w0.z); DUP2(d[3], w0.w);
        DUP2(d[4], w1.x); DUP2(d[5], w1.y); DUP2(d[6], w1.z); DUP2(d[7], w1.w);

        #pragma unroll
        for (int j = 0; j < FS; j++) {
            const unsigned long long* fp = (const unsigned long long*)&fsm2f[(i*FS + j) * 8];
            unsigned long long f0 = fp[0], f1 = fp[1], f2 = fp[2], f3 = fp[3];
            #pragma unroll
            for (int p = 0; p < 8; p++) {
                FFMA2(acc[p][0], d[p], f0);
                FFMA2(acc[p][1], d[p], f1);
                FFMA2(acc[p][2], d[p], f2);
                FFMA2(acc[p][3], d[p], f3);
            }
            if (j < FS-1) {
                float nv = rowp[j + 8];
                #pragma unroll
                for (int p = 0; p < 7; p++) d[p] = d[p+1];
                DUP2(d[7], nv);
            }
        }
    }

    int y = by*32 + ty;
    int x0 = bx*64 + tx*8;
    size_t plane = (size_t)PH * PW;
    float* cb = codes + ((size_t)b * NF) * plane + (size_t)y * PW + x0;
    #pragma unroll
    for (int p = 0; p < 8; p++) {
        float lo, hi;
        UNPK2(lo, hi, acc[p][0]); cb[p + 6*plane] = lo; cb[p + 5*plane] = hi;
        UNPK2(lo, hi, acc[p][1]); cb[p + 4*plane] = lo; cb[p + 3*plane] = hi;
        UNPK2(lo, hi, acc[p][2]); cb[p + 2*plane] = lo; cb[p + 1*plane] = hi;
        UNPK2(lo, hi, acc[p][3]); cb[p + 0*plane] = lo;
    }
}

// ===========================================================================
// Kernel 3: fp32 -> split bf16 (hi + lo residual)
// ===========================================================================
__global__ void convert_kernel(const float* __restrict__ codes) {
    int base = (blockIdx.x * 256 + threadIdx.x) * 4;
    float4 v = *(const float4*)(codes + base);
    __nv_bfloat16 h0 = __float2bfloat16(v.x);
    __nv_bfloat16 h1 = __float2bfloat16(v.y);
    __nv_bfloat16 h2 = __float2bfloat16(v.z);
    __nv_bfloat16 h3 = __float2bfloat16(v.w);
    __nv_bfloat16 l0 = __float2bfloat16(v.x - __bfloat162float(h0));
    __nv_bfloat16 l1 = __float2bfloat16(v.y - __bfloat162float(h1));
    __nv_bfloat16 l2 = __float2bfloat16(v.z - __bfloat162float(h2));
    __nv_bfloat16 l3 = __float2bfloat16(v.w - __bfloat162float(h3));
    uint2 oh, ol;
    oh.x = ((uint32_t)__bfloat16_as_ushort(h1) << 16) | __bfloat16_as_ushort(h0);
    oh.y = ((uint32_t)__bfloat16_as_ushort(h3) << 16) | __bfloat16_as_ushort(h2);
    ol.x = ((uint32_t)__bfloat16_as_ushort(l1) << 16) | __bfloat16_as_ushort(l0);
    ol.y = ((uint32_t)__bfloat16_as_ushort(l3) << 16) | __bfloat16_as_ushort(l2);
    *(uint2*)&g_hi[base] = oh;
    *(uint2*)&g_lo[base] = ol;
}

// ===========================================================================
// Kernel 4: gram via mma.sync bf16 (split hi/lo, 3 terms), cp.async pipeline.
// Block 256 thr = 8 warps (2x4), tile 128x128, K-chunk 1024, stage k=32.
// ===========================================================================
__device__ __forceinline__ void gram_load_stage(uint32_t sbase, int stage, int it,
                                                int ti, int tj, int ksp, int tid) {
    uint32_t st = sbase + stage * STAGE_BY;
    size_t kbyte = ((size_t)ksp * GKCHUNK + (size_t)it * KB) * 2;
    #pragma unroll
    for (int m = 0; m < 4; m++) {
        int rb = (m < 2) ? ti * 128 : tj * 128;
        const char* base = (m & 1) ? (const char*)g_lo : (const char*)g_hi;
        #pragma unroll
        for (int s = 0; s < 2; s++) {
            int c = tid + s * 256;            // 0..511
            int row = c >> 2, k8 = c & 3;
            int grow = rb + row;
            uint32_t dst = st + m * TILE_BY + row * (TSTRIDE*2) + k8 * 16;
            const char* src = base + (size_t)min(grow, N_ROWS-1) * (K_TOT*2) + kbyte + k8 * 16;
            if (grow < N_ROWS) cp16(dst, src);
            else               cp16z(dst, src);
        }
    }
}

__global__ __launch_bounds__(256, 1)
void gram_mma_kernel() {
    extern __shared__ char dsm[];
    uint32_t sbase = smem_u32(dsm);

    int pair = blockIdx.x;
    int ksp  = blockIdx.y;
    int ti = 0, rem = pair, cnt = GT;
    while (rem >= cnt) { rem -= cnt; ti++; cnt--; }
    int tj = ti + rem;

    int tid  = threadIdx.x;
    int wid  = tid >> 5, lane = tid & 31;
    int warp_m = wid & 1;        // 2 m-tiles of 64
    int warp_n = wid >> 1;       // 4 n-tiles of 32

    float acc[4][4][4];
    #pragma unroll
    for (int mi = 0; mi < 4; mi++)
        #pragma unroll
        for (int ni = 0; ni < 4; ni++)
            #pragma unroll
            for (int q = 0; q < 4; q++) acc[mi][ni][q] = 0.f;

    // per-lane ldmatrix base offsets (within a matrix tile)
    uint32_t a_off = (uint32_t)((warp_m*64 + (lane & 15)) * (TSTRIDE*2) + ((lane >> 4) & 1) * 16);
    uint32_t b_off = (uint32_t)((warp_n*32 + (lane & 7))  * (TSTRIDE*2) + ((lane >> 3) & 1) * 16);

    gram_load_stage(sbase, 0, 0, ti, tj, ksp, tid);
    cp_commit();

    for (int it = 0; it < KITERS; it++) {
        if (it + 1 < KITERS) {
            gram_load_stage(sbase, (it + 1) & 1, it + 1, ti, tj, ksp, tid);
            cp_commit();
            cp_wait1();
        } else {
            cp_wait0();
        }
        __syncthreads();

        uint32_t st   = sbase + (it & 1) * STAGE_BY;
        uint32_t aHi  = st;
        uint32_t aLo  = st + TILE_BY;
        uint32_t bHi  = st + 2 * TILE_BY;
        uint32_t bLo  = st + 3 * TILE_BY;

        #pragma unroll
        for (int k16 = 0; k16 < 2; k16++) {
            uint32_t kadd = (uint32_t)(k16 * 32);
            uint32_t ahi[4][4], alo[4][4];
            #pragma unroll
            for (int mi = 0; mi < 4; mi++) {
                uint32_t off = a_off + kadd + (uint32_t)(mi * 16 * (TSTRIDE*2));
                ldm_x4(ahi[mi], aHi + off);
                ldm_x4(alo[mi], aLo + off);
            }
            uint32_t bhi[4][2], blo[4][2];
            #pragma unroll
            for (int ni = 0; ni < 4; ni++) {
                uint32_t off = b_off + kadd + (uint32_t)(ni * 8 * (TSTRIDE*2));
                ldm_x2(bhi[ni], bHi + off);
                ldm_x2(blo[ni], bLo + off);
            }
            #pragma unroll
            for (int mi = 0; mi < 4; mi++)
                #pragma unroll
                for (int ni = 0; ni < 4; ni++) {
                    mma_bf16(acc[mi][ni], ahi[mi], bhi[ni]);
                    mma_bf16(acc[mi][ni], ahi[mi], blo[ni]);
                    mma_bf16(acc[mi][ni], alo[mi], bhi[ni]);
                }
        }
        __syncthreads();
    }

    float* dst = &g_gpart[pair][ksp][0];
    int r0 = warp_m * 64;
    int c0 = warp_n * 32;
    #pragma unroll
    for (int mi = 0; mi < 4; mi++) {
        #pragma unroll
        for (int ni = 0; ni < 4; ni++) {
            int row = r0 + mi*16 + (lane >> 2);
            int col = c0 + ni*8 + (lane & 3) * 2;
            *(float2*)&dst[row * 128 + col]       = make_float2(acc[mi][ni][0], acc[mi][ni][1]);
            *(float2*)&dst[(row + 8) * 128 + col] = make_float2(acc[mi][ni][2], acc[mi][ni][3]);
        }
    }
}

// ===========================================================================
// Kernel 5: reduce K-splits, scale, symmetric write
// ===========================================================================
__global__ void gram_reduce_kernel(float* __restrict__ gram) {
    int idx = blockIdx.x * blockDim.x + threadIdx.x;
    if (idx >= GPAIRS * 128 * 128) return;
    int pair = idx >> 14;
    int e    = idx & 16383;
    int ii = e >> 7, jj = e & 127;

    int ti = 0, rem = pair, cnt = GT;
    while (rem >= cnt) { rem -= cnt; ti++; cnt--; }
    int tj = ti + rem;

    int gi = ti * 128 + ii;
    int gj = tj * 128 + jj;
    if (gi >= N_ROWS || gj >= N_ROWS) return;

    float s = 0.f;
    #pragma unroll
    for (int k = 0; k < GKSPLIT; k++) s += g_gpart[pair][k][e];
    s *= (1.0f / 14680064.0f);

    gram[gi * N_ROWS + gj] = s;
    gram[gj * N_ROWS + gi] = s;
}

// ===========================================================================
extern "C" void kernel_launch(void* const* d_in, const int* in_sizes, int n_in,
                              void* d_out, int out_size) {
    const float* image = (const float*)d_in[0];
    const float* pupil = (const float*)d_in[1];
    const float* iris  = (const float*)d_in[2];
    const float* filt  = (const float*)d_in[3];

    float* out   = (float*)d_out;
    float* codes = out + CODES_OFF;
    float* gram  = out + GRAM_OFF;
    float* polar = out + POLAR_OFF;

    cudaFuncSetAttribute(gram_mma_kernel,
                         cudaFuncAttributeMaxDynamicSharedMemorySize, GSMEM);

    polar_kernel<<<(B * PH * PW) / 256, 256>>>(image, pupil, iris, polar);
    conv_kernel<<<dim3(PW/64, PH/32, B), dim3(8, 32)>>>(polar, filt, codes);
    convert_kernel<<<(N_ROWS * K_TOT) / 1024, 256>>>(codes);
    gram_mma_kernel<<<dim3(GPAIRS, GKSPLIT), 256, GSMEM>>>();
    gram_reduce_kernel<<<(GPAIRS * 128 * 128 + 255) / 256, 256>>>(gram);
}

// round 5
// speedup vs baseline: 1.8596x; 1.0526x over previous
#include <cuda_runtime.h>
#include <cuda_bf16.h>
#include <cstdint>

#define B   64
#define H   480
#define W   640
#define PH  64
#define PW  512
#define FS  15
#define NF  7
#define RAD 7

#define K_TOT   (PH*PW)          // 32768
#define N_ROWS  (B*NF)           // 448

#define CODES_OFF 0
#define GRAM_OFF  (B*NF*PH*PW)                // 14680064
#define POLAR_OFF (GRAM_OFF + N_ROWS*N_ROWS)  // 14880768

// ---- gram tiling ----
#define GT       4
#define GPAIRS   10
#define GKSPLIT  32
#define GKCHUNK  (K_TOT/GKSPLIT)    // 1024
#define KB       32
#define KITERS   (GKCHUNK/KB)       // 32

#define TSTRIDE  40                 // bf16 per smem row (80B)
#define TILE_BY  (128*TSTRIDE*2)    // 10240 B
#define STAGE_BY (4*TILE_BY)        // 40960 B
#define NSTAGE   4
#define GSMEM    (NSTAGE*STAGE_BY)  // 163840 B

// scratch (device-code references ONLY — host-side symbol use is a silent
// ATS write to host BSS on GB300)
__device__ __nv_bfloat16 g_hi[(size_t)N_ROWS * K_TOT];
__device__ __nv_bfloat16 g_lo[(size_t)N_ROWS * K_TOT];
__device__ float g_gpart[GPAIRS][GKSPLIT][128*128];

// ===========================================================================
// helpers
// ===========================================================================
__device__ __forceinline__ uint32_t smem_u32(const void* p) {
    uint32_t a;
    asm("{ .reg .u64 t; cvta.to.shared.u64 t, %1; cvt.u32.u64 %0, t; }" : "=r"(a) : "l"(p));
    return a;
}

#define FFMA2(d, a, b) \
    asm("fma.rn.f32x2 %0, %1, %2, %0;" : "+l"(d) : "l"(a), "l"(b))
#define PACK2(d, a, b) \
    asm("mov.b64 %0, {%1, %2};" : "=l"(d) : "f"(a), "f"(b))
#define UNPK2(lo, hi, v) \
    asm("mov.b64 {%0, %1}, %2;" : "=f"(lo), "=f"(hi) : "l"(v))

__device__ __forceinline__ void cp16(uint32_t dst, const void* src) {
    asm volatile("cp.async.ca.shared.global [%0], [%1], 16;" :: "r"(dst), "l"(src));
}
__device__ __forceinline__ void cp16z(uint32_t dst, const void* src) {
    asm volatile("cp.async.ca.shared.global [%0], [%1], 16, 0;" :: "r"(dst), "l"(src));
}
__device__ __forceinline__ void cp_commit() { asm volatile("cp.async.commit_group;" ::: "memory"); }
__device__ __forceinline__ void cp_wait2()  { asm volatile("cp.async.wait_group 2;" ::: "memory"); }

__device__ __forceinline__ void ldm_x4(uint32_t* r, uint32_t addr) {
    asm volatile("ldmatrix.sync.aligned.m8n8.x4.shared.b16 {%0,%1,%2,%3}, [%4];"
        : "=r"(r[0]), "=r"(r[1]), "=r"(r[2]), "=r"(r[3]) : "r"(addr));
}
__device__ __forceinline__ void mma_bf16(float* c, const uint32_t* a, uint32_t b0, uint32_t b1) {
    asm volatile("mma.sync.aligned.m16n8k16.row.col.f32.bf16.bf16.f32 "
        "{%0,%1,%2,%3}, {%4,%5,%6,%7}, {%8,%9}, {%0,%1,%2,%3};"
        : "+f"(c[0]), "+f"(c[1]), "+f"(c[2]), "+f"(c[3])
        : "r"(a[0]), "r"(a[1]), "r"(a[2]), "r"(a[3]), "r"(b0), "r"(b1));
}

// ===========================================================================
// Kernel 1: polar bilinear resample
// ===========================================================================
__global__ void polar_kernel(const float* __restrict__ img,
                             const float* __restrict__ pupil,
                             const float* __restrict__ iris,
                             float* __restrict__ polar) {
    int idx = blockIdx.x * blockDim.x + threadIdx.x;
    if (idx >= B * PH * PW) return;
    int col = idx % PW;
    int row = (idx / PW) % PH;
    int b   = idx / (PH * PW);

    float theta = 6.283185307179586f * (float)(col + 1) * (1.0f / (float)PW);
    float ct = cosf(theta), st = sinf(theta);

    float pcx = pupil[b*3+0], pcy = pupil[b*3+1], pr = pupil[b*3+2];
    float icx = iris [b*3+0], icy = iris [b*3+1], ir = iris [b*3+2];

    float px = pcx + pr * ct;
    float py = pcy + pr * st;
    float ix = icx + ir * ct;
    float iy = icy + ir * st;

    float rad = (float)row / (float)(PH - 1);
    float xg = (1.0f - rad) * px + rad * ix;
    float yg = (1.0f - rad) * py + rad * iy;

    float x = fminf(fmaxf(xg, 0.0f), (float)(W - 1));
    float y = fminf(fmaxf(yg, 0.0f), (float)(H - 1));

    float xn = x / (float)(W - 1) * 2.0f - 1.0f;
    float yn = y / (float)(H - 1) * 2.0f - 1.0f;
    float gx = ((xn + 1.0f) * 0.5f * (float)W - 0.5f) / (float)(W - 1) * 2.0f - 1.0f;
    float gy = ((yn + 1.0f) * 0.5f * (float)H - 0.5f) / (float)(H - 1) * 2.0f - 1.0f;
    float sx = ((gx + 1.0f) * (float)W - 1.0f) * 0.5f;
    float sy = ((gy + 1.0f) * (float)H - 1.0f) * 0.5f;

    float x0f = floorf(sx), y0f = floorf(sy);
    float wx = sx - x0f, wy = sy - y0f;
    int x0 = (int)x0f, y0 = (int)y0f;

    const float* im = img + (size_t)b * H * W;

    float v00 = 0.f, v01 = 0.f, v10 = 0.f, v11 = 0.f;
    bool xv0 = (x0 >= 0) && (x0 < W);
    bool xv1 = (x0+1 >= 0) && (x0+1 < W);
    bool yv0 = (y0 >= 0) && (y0 < H);
    bool yv1 = (y0+1 >= 0) && (y0+1 < H);
    int x0c = min(max(x0, 0), W-1), x1c = min(max(x0+1, 0), W-1);
    int y0c = min(max(y0, 0), H-1), y1c = min(max(y0+1, 0), H-1);
    if (xv0 && yv0) v00 = im[y0c*W + x0c] * 255.0f;
    if (xv1 && yv0) v01 = im[y0c*W + x1c] * 255.0f;
    if (xv0 && yv1) v10 = im[y1c*W + x0c] * 255.0f;
    if (xv1 && yv1) v11 = im[y1c*W + x1c] * 255.0f;

    float v = v00*(1.0f-wx)*(1.0f-wy) + v01*wx*(1.0f-wy)
            + v10*(1.0f-wx)*wy        + v11*wx*wy;
    polar[idx] = v;
}

// ===========================================================================
// Kernel 2: 15x15 wrap conv, pixel-pair f32x2 packing, fused bf16 split.
// Block (16,16): 4 px per thread (2 pairs), 7 filters. Tile 64x16 outputs.
// Writes g_hi/g_lo through the DEVICE symbols (not kernel args!).
// ===========================================================================
#define CTS 80
__global__ __launch_bounds__(256, 2)
void conv_kernel(const float* __restrict__ polar,
                 const float* __restrict__ filt,
                 float* __restrict__ codes) {
    __shared__ __align__(16) float tile[30 * CTS];       // 30 rows x 78 used
    __shared__ __align__(16) float2 fsm2[FS*FS*8];       // dup'd filter taps

    int tx = threadIdx.x;            // 0..15
    int ty = threadIdx.y;            // 0..15
    int tid = ty * 16 + tx;
    int bx = blockIdx.x;             // 0..7
    int by = blockIdx.y;             // 0..3
    int b  = blockIdx.z;

    for (int e = tid; e < FS*FS*8; e += 256) {
        int tap = e >> 3, f = e & 7;
        float w = (f < NF) ? filt[tap*NF + f] : 0.0f;
        fsm2[e] = make_float2(w, w);
    }
    const float* pb = polar + (size_t)b * PH * PW;
    for (int e = tid; e < 30 * 78; e += 256) {
        int rr = e / 78, cc = e % 78;
        int gy = (by*16 + 64 - RAD + rr) & (PH - 1);
        int gx = (bx*64 + 512 - RAD + cc) & (PW - 1);
        tile[rr*CTS + cc] = pb[gy * PW + gx];
    }
    __syncthreads();

    unsigned long long acc[2][NF];
    #pragma unroll
    for (int q = 0; q < 2; q++)
        #pragma unroll
        for (int f = 0; f < NF; f++) acc[q][f] = 0ULL;

    #pragma unroll 1
    for (int i = 0; i < FS; i++) {
        const float* rp = &tile[(ty + i) * CTS + tx * 4];
        float px[18];
        float4 v0 = *(const float4*)(rp + 0);
        float4 v1 = *(const float4*)(rp + 4);
        float4 v2 = *(const float4*)(rp + 8);
        float4 v3 = *(const float4*)(rp + 12);
        float2 v4 = *(const float2*)(rp + 16);
        px[0]=v0.x; px[1]=v0.y; px[2]=v0.z; px[3]=v0.w;
        px[4]=v1.x; px[5]=v1.y; px[6]=v1.z; px[7]=v1.w;
        px[8]=v2.x; px[9]=v2.y; px[10]=v2.z; px[11]=v2.w;
        px[12]=v3.x; px[13]=v3.y; px[14]=v3.z; px[15]=v3.w;
        px[16]=v4.x; px[17]=v4.y;

        #pragma unroll
        for (int j = 0; j < FS; j++) {
            unsigned long long p0, p1;
            PACK2(p0, px[j],   px[j+1]);
            PACK2(p1, px[j+2], px[j+3]);
            const unsigned long long* fp = (const unsigned long long*)&fsm2[(i*FS + j) * 8];
            #pragma unroll
            for (int f = 0; f < NF; f++) {
                unsigned long long w = fp[f];
                FFMA2(acc[0][f], p0, w);
                FFMA2(acc[1][f], p1, w);
            }
        }
    }

    int y = by*16 + ty;
    int x0 = bx*64 + tx*4;
    size_t plane = (size_t)PH * PW;
    size_t base = ((size_t)b * NF) * plane + (size_t)y * PW + x0;
    #pragma unroll
    for (int f = 0; f < NF; f++) {
        int o = 6 - f;
        float a0, a1, a2, a3;
        UNPK2(a0, a1, acc[0][f]);
        UNPK2(a2, a3, acc[1][f]);
        size_t off = base + (size_t)o * plane;
        *(float4*)&codes[off] = make_float4(a0, a1, a2, a3);

        __nv_bfloat16 h0 = __float2bfloat16(a0);
        __nv_bfloat16 h1 = __float2bfloat16(a1);
        __nv_bfloat16 h2 = __float2bfloat16(a2);
        __nv_bfloat16 h3 = __float2bfloat16(a3);
        __nv_bfloat16 l0 = __float2bfloat16(a0 - __bfloat162float(h0));
        __nv_bfloat16 l1 = __float2bfloat16(a1 - __bfloat162float(h1));
        __nv_bfloat16 l2 = __float2bfloat16(a2 - __bfloat162float(h2));
        __nv_bfloat16 l3 = __float2bfloat16(a3 - __bfloat162float(h3));
        uint2 oh, ol;
        oh.x = ((uint32_t)__bfloat16_as_ushort(h1) << 16) | __bfloat16_as_ushort(h0);
        oh.y = ((uint32_t)__bfloat16_as_ushort(h3) << 16) | __bfloat16_as_ushort(h2);
        ol.x = ((uint32_t)__bfloat16_as_ushort(l1) << 16) | __bfloat16_as_ushort(l0);
        ol.y = ((uint32_t)__bfloat16_as_ushort(l3) << 16) | __bfloat16_as_ushort(l2);
        *(uint2*)&g_hi[off] = oh;   // device symbol, valid
        *(uint2*)&g_lo[off] = ol;
    }
}

// ===========================================================================
// Kernel 3: gram via mma.sync bf16 (hi/lo, 3 terms), 16 warps, 4-stage ring.
// ===========================================================================
__device__ __forceinline__ void gram_load_stage(uint32_t sbase, int stage, int it,
                                                int ti, int tj, int ksp, int tid, int nm) {
    uint32_t st = sbase + stage * STAGE_BY;
    size_t kbyte = ((size_t)ksp * GKCHUNK + (size_t)it * KB) * 2;
    int row = tid >> 2, k8 = tid & 3;
    uint32_t doff = (uint32_t)(row * (TSTRIDE*2) + k8 * 16);
    #pragma unroll
    for (int m = 0; m < 4; m++) {
        if (m >= nm) break;
        int grow = ((m < 2) ? ti : tj) * 128 + row;
        const char* matbase = (m & 1) ? (const char*)g_lo : (const char*)g_hi;
        uint32_t dst = st + m * TILE_BY + doff;
        const char* src = matbase + (size_t)min(grow, N_ROWS-1) * (K_TOT*2) + kbyte + k8 * 16;
        if (grow < N_ROWS) cp16(dst, src);
        else               cp16z(dst, src);
    }
}

__global__ __launch_bounds__(512, 1)
void gram_mma_kernel() {
    extern __shared__ char dsm[];
    uint32_t sbase = smem_u32(dsm);

    int pair = blockIdx.x;
    int ksp  = blockIdx.y;
    int ti = 0, rem = pair, cnt = GT;
    while (rem >= cnt) { rem -= cnt; ti++; cnt--; }
    int tj = ti + rem;
    bool diag = (ti == tj);
    int nm = diag ? 2 : 4;

    int tid  = threadIdx.x;
    int wid  = tid >> 5, lane = tid & 31;
    int warp_m = wid & 3;        // 4 m-tiles of 32
    int warp_n = wid >> 2;       // 4 n-tiles of 32

    float acc[2][4][4];
    #pragma unroll
    for (int mi = 0; mi < 2; mi++)
        #pragma unroll
        for (int ni = 0; ni < 4; ni++)
            #pragma unroll
            for (int q = 0; q < 4; q++) acc[mi][ni][q] = 0.f;

    uint32_t a_off = (uint32_t)((warp_m*32 + (lane & 15)) * (TSTRIDE*2) + ((lane >> 4) & 1) * 16);
    uint32_t b_off = (uint32_t)((warp_n*32 + (lane & 15)) * (TSTRIDE*2) + ((lane >> 4) & 1) * 16);

    // prologue: 3 stages in flight
    #pragma unroll
    for (int p = 0; p < 3; p++) {
        gram_load_stage(sbase, p, p, ti, tj, ksp, tid, nm);
        cp_commit();
    }

    for (int it = 0; it < KITERS; it++) {
        cp_wait2();
        __syncthreads();

        uint32_t st  = sbase + (it & 3) * STAGE_BY;
        uint32_t aHi = st;
        uint32_t aLo = st + TILE_BY;
        uint32_t bHi = diag ? st           : st + 2*TILE_BY;
        uint32_t bLo = diag ? st + TILE_BY : st + 3*TILE_BY;

        #pragma unroll
        for (int k16 = 0; k16 < 2; k16++) {
            uint32_t kadd = (uint32_t)(k16 * 32);
            uint32_t ahi[2][4], alo[2][4];
            #pragma unroll
            for (int mi = 0; mi < 2; mi++) {
                ldm_x4(ahi[mi], aHi + a_off + kadd + mi*16*(TSTRIDE*2));
                ldm_x4(alo[mi], aLo + a_off + kadd + mi*16*(TSTRIDE*2));
            }
            uint32_t bhiR[2][4], bloR[2][4];
            #pragma unroll
            for (int n2 = 0; n2 < 2; n2++) {
                ldm_x4(bhiR[n2], bHi + b_off + kadd + n2*16*(TSTRIDE*2));
                ldm_x4(bloR[n2], bLo + b_off + kadd + n2*16*(TSTRIDE*2));
            }
            #pragma unroll
            for (int mi = 0; mi < 2; mi++)
                #pragma unroll
                for (int ni = 0; ni < 4; ni++) {
                    int n2 = ni >> 1, sel = ni & 1;
                    uint32_t bh0 = bhiR[n2][sel], bh1 = bhiR[n2][sel+2];
                    uint32_t bl0 = bloR[n2][sel], bl1 = bloR[n2][sel+2];
                    mma_bf16(acc[mi][ni], ahi[mi], bh0, bh1);
                    mma_bf16(acc[mi][ni], ahi[mi], bl0, bl1);
                    mma_bf16(acc[mi][ni], alo[mi], bh0, bh1);
                }
        }

        int nx = it + 3;
        if (nx < KITERS) gram_load_stage(sbase, nx & 3, nx, ti, tj, ksp, tid, nm);
        cp_commit();
    }

    float* dst = &g_gpart[pair][ksp][0];
    int r0 = warp_m * 32;
    int c0 = warp_n * 32;
    #pragma unroll
    for (int mi = 0; mi < 2; mi++) {
        #pragma unroll
        for (int ni = 0; ni < 4; ni++) {
            int row = r0 + mi*16 + (lane >> 2);
            int col = c0 + ni*8 + (lane & 3) * 2;
            *(float2*)&dst[row * 128 + col]       = make_float2(acc[mi][ni][0], acc[mi][ni][1]);
            *(float2*)&dst[(row + 8) * 128 + col] = make_float2(acc[mi][ni][2], acc[mi][ni][3]);
        }
    }
}

// ===========================================================================
// Kernel 4: reduce K-splits, scale, symmetric write
// ===========================================================================
__global__ void gram_reduce_kernel(float* __restrict__ gram) {
    int idx = blockIdx.x * blockDim.x + threadIdx.x;
    if (idx >= GPAIRS * 128 * 128) return;
    int pair = idx >> 14;
    int e    = idx & 16383;
    int ii = e >> 7, jj = e & 127;

    int ti = 0, rem = pair, cnt = GT;
    while (rem >= cnt) { rem -= cnt; ti++; cnt--; }
    int tj = ti + rem;

    int gi = ti * 128 + ii;
    int gj = tj * 128 + jj;
    if (gi >= N_ROWS || gj >= N_ROWS) return;

    float s = 0.f;
    #pragma unroll
    for (int k = 0; k < GKSPLIT; k++) s += g_gpart[pair][k][e];
    s *= (1.0f / 14680064.0f);

    gram[gi * N_ROWS + gj] = s;
    gram[gj * N_ROWS + gi] = s;
}

// ===========================================================================
extern "C" void kernel_launch(void* const* d_in, const int* in_sizes, int n_in,
                              void* d_out, int out_size) {
    const float* image = (const float*)d_in[0];
    const float* pupil = (const float*)d_in[1];
    const float* iris  = (const float*)d_in[2];
    const float* filt  = (const float*)d_in[3];

    float* out   = (float*)d_out;
    float* codes = out + CODES_OFF;
    float* gram  = out + GRAM_OFF;
    float* polar = out + POLAR_OFF;

    cudaFuncSetAttribute(gram_mma_kernel,
                         cudaFuncAttributeMaxDynamicSharedMemorySize, GSMEM);

    polar_kernel<<<(B * PH * PW) / 256, 256>>>(image, pupil, iris, polar);
    conv_kernel<<<dim3(PW/64, PH/16, B), dim3(16, 16)>>>(polar, filt, codes);
    gram_mma_kernel<<<dim3(GPAIRS, GKSPLIT), 512, GSMEM>>>();
    gram_reduce_kernel<<<(GPAIRS * 128 * 128 + 255) / 256, 256>>>(gram);
}